// round 15
// baseline (speedup 1.0000x reference)
#include <cuda_runtime.h>
#include <cuda_fp16.h>
#include <cstdint>

// Problem constants
#define BB 2
#define CC 1024
#define LL 2048
#define HH 16
#define HD 64
#define BCL (BB*CC*LL)               // 4,194,304 elems
#define NBH (BB*HH)                  // 32
#define SROWS ((size_t)NBH * LL)     // 65536
#define SELEMS (SROWS * LL)          // 134,217,728 elems (256 MB fp16)
#define WELEMS (CC*CC)               // 1,048,576 per weight
#define XS_SCALE 256.0f              // pre-scale for x/Z (avoid fp16 subnormals)

// Scratch (device globals — runtime allocation is forbidden)
__device__ __half g_X16 [BCL];          // x fp16
__device__ __half g_K16 [BCL];          // K proj fp16
__device__ __half g_Q16 [BCL];          // Q proj fp16
__device__ __half g_A16 [BCL];          // attn out fp16
__device__ float  g_Y   [BCL];          // y fp32 (residual)
__device__ __half g_Y16 [BCL];          // y fp16
__device__ __half g_T16 [BCL];          // relu(c1(y)) fp16
__device__ __half g_S   [SELEMS];       // E = exp(scores) fp16
__device__ float  g_Z   [SROWS];        // row sums of E
__device__ __half g_W16 [5*WELEMS];     // weights fp16 (kw,qw,pw,c1w,c2w)

// ---------------------------------------------------------------------------
// helpers
// ---------------------------------------------------------------------------
__device__ __forceinline__ uint32_t smem_u32(const void* p) {
    uint32_t a;
    asm("{ .reg .u64 t; cvta.to.shared.u64 t, %1; cvt.u32.u64 %0, t; }"
        : "=r"(a) : "l"(p));
    return a;
}
__device__ __forceinline__ uint32_t h2(float a, float b) {
    __half2 t = __floats2half2_rn(a, b);
    return *reinterpret_cast<uint32_t*>(&t);
}

__device__ __forceinline__ void ldsm_x4(uint32_t r[4], uint32_t addr) {
    asm volatile("ldmatrix.sync.aligned.m8n8.x4.shared.b16 {%0,%1,%2,%3}, [%4];"
                 : "=r"(r[0]), "=r"(r[1]), "=r"(r[2]), "=r"(r[3]) : "r"(addr));
}
__device__ __forceinline__ void ldsm_x4_t(uint32_t r[4], uint32_t addr) {
    asm volatile("ldmatrix.sync.aligned.m8n8.x4.trans.shared.b16 {%0,%1,%2,%3}, [%4];"
                 : "=r"(r[0]), "=r"(r[1]), "=r"(r[2]), "=r"(r[3]) : "r"(addr));
}
__device__ __forceinline__ void mma_f16(float c[4], const uint32_t a[4],
                                        const uint32_t b[2]) {
    asm volatile("mma.sync.aligned.m16n8k16.row.col.f32.f16.f16.f32 "
                 "{%0,%1,%2,%3}, {%4,%5,%6,%7}, {%8,%9}, {%0,%1,%2,%3};"
                 : "+f"(c[0]), "+f"(c[1]), "+f"(c[2]), "+f"(c[3])
                 : "r"(a[0]), "r"(a[1]), "r"(a[2]), "r"(a[3]),
                   "r"(b[0]), "r"(b[1]));
}

// ---------------------------------------------------------------------------
// fused prep: cvt x, cvt 5 weights, zero Z. One launch.
// ---------------------------------------------------------------------------
#define XBLK (BCL/4/256)            // 4096
#define WBLK (WELEMS/4/256)         // 1024
#define ZBLK (SROWS/4/256)          // 64
#define PREP_BLOCKS (XBLK + 5*WBLK + ZBLK)   // 9280

__global__ __launch_bounds__(256)
void prep_kernel(const float* __restrict__ x,
                 const float* __restrict__ kw, const float* __restrict__ qw,
                 const float* __restrict__ pw, const float* __restrict__ c1w,
                 const float* __restrict__ c2w,
                 __half* __restrict__ X16, __half* __restrict__ W16,
                 float* __restrict__ Z)
{
    const int blk = blockIdx.x;
    if (blk < XBLK) {
        const unsigned i = blk * 256u + threadIdx.x;
        float4 v = reinterpret_cast<const float4*>(x)[i];
        reinterpret_cast<uint2*>(X16)[i] = make_uint2(h2(v.x, v.y), h2(v.z, v.w));
    } else if (blk < XBLK + 5 * WBLK) {
        const int wi = (blk - XBLK) / WBLK;
        const int wb = (blk - XBLK) % WBLK;
        const float* src = (wi == 0) ? kw : (wi == 1) ? qw : (wi == 2) ? pw
                          : (wi == 3) ? c1w : c2w;
        const unsigned i = wb * 256u + threadIdx.x;
        float4 v = reinterpret_cast<const float4*>(src)[i];
        reinterpret_cast<uint2*>(W16 + (size_t)wi * WELEMS)[i] =
            make_uint2(h2(v.x, v.y), h2(v.z, v.w));
    } else {
        const unsigned i = (blk - XBLK - 5 * WBLK) * 256u + threadIdx.x;
        reinterpret_cast<float4*>(Z)[i] = make_float4(0.f, 0.f, 0.f, 0.f);
    }
}

// ---------------------------------------------------------------------------
// HMMA conv1x1, fp16 operands, fp32 accumulate.
// 128 threads, 4 warps, warp tile 64x64 (block 128x128): halves LDS re-reads.
// KQ=true: stacked [2C, C] weight (kw‖qw); o0 >= CC -> Q16/qb.
// OMODE: 0 = fp16 O16 only; 1 = fp32 Out AND fp16 O16; 2 = fp32 only.
// ---------------------------------------------------------------------------
#define APITCH 72
#define BPITCH 136
#define SM_B (128 * APITCH)
#define CONV_SMEM ((128 * APITCH + 64 * BPITCH) * 2)   // 35,840 B

template<bool KQ, bool RELU, int NADD, int OMODE>
__global__ __launch_bounds__(128)
void conv_mma_kernel(const __half* __restrict__ W16,
                     const float* __restrict__ bias,
                     const float* __restrict__ bias2,
                     const __half* __restrict__ B16,
                     float* __restrict__ Out,
                     __half* __restrict__ O16,
                     __half* __restrict__ O16b,
                     const float* __restrict__ A1,
                     const float* __restrict__ A2)
{
    extern __shared__ __align__(16) __half smem[];
    __half* sA = smem;
    __half* sB = smem + SM_B;
    const uint32_t uA = smem_u32(sA);
    const uint32_t uB = smem_u32(sB);

    const int b  = blockIdx.z;
    int o0 = blockIdx.y * 128;
    const int l0 = blockIdx.x * 128;
    const size_t boff = (size_t)b * CC * LL;

    const float* biasp = bias;
    __half* O16p = O16;
    const int wrow0 = o0;
    if (KQ && o0 >= CC) {
        biasp = bias2;
        O16p = O16b;
        o0 -= CC;
    }

    const int tid  = threadIdx.x;
    const int wid  = tid >> 5;
    const int lane = tid & 31;
    const int wm   = wid & 1;          // 2 o-groups of 64
    const int wn   = wid >> 1;         // 2 l-groups of 64

    // loaders (uint4 = 8 fp16)
    const int ar  = tid >> 3;          // A row base 0..15 (8 passes of 16)
    const int ac8 = (tid & 7) * 8;     // A col (full 64-col row per 8 lanes)
    const int br  = tid >> 4;          // B row base 0..7 (8 passes of 8)
    const int bc8 = (tid & 15) * 8;    // B col (full 128-col row per 16 lanes)

    const int a_row = wm * 64 + (lane & 15);
    const int a_col = ((lane >> 4) & 1) * 8;
    const int b_row = (lane & 15);
    const int b_colb = wn * 64 + ((lane >> 4) & 1) * 8;

    float acc[4][8][4];
    #pragma unroll
    for (int mi = 0; mi < 4; mi++)
        #pragma unroll
        for (int ni = 0; ni < 8; ni++)
            #pragma unroll
            for (int q = 0; q < 4; q++) acc[mi][ni][q] = 0.0f;

    for (int ci = 0; ci < CC / 64; ci++) {
        const int c0 = ci * 64;
        if (ci) __syncthreads();

        #pragma unroll
        for (int p = 0; p < 8; p++) {
            const int row = ar + p * 16;
            *(uint4*)&sA[row * APITCH + ac8] =
                *(const uint4*)&W16[(size_t)(wrow0 + row) * CC + c0 + ac8];
        }
        #pragma unroll
        for (int p = 0; p < 8; p++) {
            const int row = br + p * 8;
            *(uint4*)&sB[row * BPITCH + bc8] =
                *(const uint4*)&B16[boff + (size_t)(c0 + row) * LL + l0 + bc8];
        }
        __syncthreads();

        #pragma unroll
        for (int ks = 0; ks < 4; ks++) {
            const int kb = ks * 16;
            uint32_t af[4][4], bf[8][2];

            #pragma unroll
            for (int mi = 0; mi < 4; mi++) {
                const uint32_t off =
                    (uint32_t)((a_row + mi * 16) * APITCH + kb + a_col) * 2;
                ldsm_x4(af[mi], uA + off);
            }
            #pragma unroll
            for (int nq = 0; nq < 4; nq++) {
                const uint32_t off =
                    (uint32_t)((kb + b_row) * BPITCH + b_colb + nq * 16) * 2;
                uint32_t th[4];
                ldsm_x4_t(th, uB + off);
                bf[nq * 2 + 0][0] = th[0]; bf[nq * 2 + 0][1] = th[1];
                bf[nq * 2 + 1][0] = th[2]; bf[nq * 2 + 1][1] = th[3];
            }

            #pragma unroll
            for (int mi = 0; mi < 4; mi++)
                #pragma unroll
                for (int ni = 0; ni < 8; ni++)
                    mma_f16(acc[mi][ni], af[mi], bf[ni]);
        }
    }

    const int r = lane >> 2;
    const int g = lane & 3;

    #pragma unroll
    for (int mi = 0; mi < 4; mi++) {
        const int o1 = o0 + wm * 64 + mi * 16 + r;
        const int o2 = o1 + 8;
        const float bv1 = __ldg(&biasp[o1]);
        const float bv2 = __ldg(&biasp[o2]);
        #pragma unroll
        for (int ni = 0; ni < 8; ni++) {
            const int l = l0 + wn * 64 + ni * 8 + g * 2;
            float2 v01 = make_float2(acc[mi][ni][0] + bv1, acc[mi][ni][1] + bv1);
            float2 v23 = make_float2(acc[mi][ni][2] + bv2, acc[mi][ni][3] + bv2);
            if (RELU) {
                v01.x = fmaxf(v01.x, 0.f); v01.y = fmaxf(v01.y, 0.f);
                v23.x = fmaxf(v23.x, 0.f); v23.y = fmaxf(v23.y, 0.f);
            }
            const size_t i1 = boff + (size_t)o1 * LL + l;
            const size_t i2 = boff + (size_t)o2 * LL + l;
            if (NADD >= 1) {
                float2 a1v = *(const float2*)&A1[i1];
                float2 a2v = *(const float2*)&A1[i2];
                v01.x += a1v.x; v01.y += a1v.y;
                v23.x += a2v.x; v23.y += a2v.y;
            }
            if (NADD >= 2) {
                float2 a1v = *(const float2*)&A2[i1];
                float2 a2v = *(const float2*)&A2[i2];
                v01.x += a1v.x; v01.y += a1v.y;
                v23.x += a2v.x; v23.y += a2v.y;
            }
            if (OMODE >= 1) {
                *(float2*)&Out[i1] = v01;
                *(float2*)&Out[i2] = v23;
            }
            if (OMODE <= 1) {
                *(uint32_t*)&O16p[i1] = h2(v01.x, v01.y);
                *(uint32_t*)&O16p[i2] = h2(v23.x, v23.y);
            }
        }
    }
}

// ---------------------------------------------------------------------------
// HMMA scores -> E = exp(scores/1024) (fp16) + per-row sums Z (atomicAdd).
// (R11-verified, unchanged.)
// ---------------------------------------------------------------------------
#define SPITCH 136
#define SC_Q (64 * SPITCH)
#define SCORES_SMEM (2 * 64 * SPITCH * 2)   // 34,816 B

__global__ __launch_bounds__(256)
void scores_mma_kernel(const __half* __restrict__ K16,
                       const __half* __restrict__ Q16,
                       __half* __restrict__ S,
                       float* __restrict__ Z)
{
    extern __shared__ __align__(16) __half smem[];
    __half* sK = smem;
    __half* sQ = smem + SC_Q;
    const uint32_t uK = smem_u32(sK);
    const uint32_t uQ = smem_u32(sQ);

    const int bh = blockIdx.z;
    const int b = bh >> 4, h = bh & 15;
    const int l0 = blockIdx.y * 128;
    const int m0 = blockIdx.x * 128;

    const size_t hoff = (size_t)b * CC * LL + (size_t)h * HD * LL;
    __half* Sb = S + (size_t)bh * LL * LL;
    float* Zb = Z + (size_t)bh * LL;

    const int tid  = threadIdx.x;
    const int wid  = tid >> 5;
    const int lane = tid & 31;
    const int wm   = wid & 3;
    const int wn   = wid >> 2;

    const int lr  = tid >> 5;
    const int lc4 = (tid & 31) * 4;

    #pragma unroll
    for (int p = 0; p < 8; p++) {
        const int row = lr + p * 8;
        *(uint2*)&sK[row * SPITCH + lc4] =
            *(const uint2*)&K16[hoff + (size_t)row * LL + l0 + lc4];
        *(uint2*)&sQ[row * SPITCH + lc4] =
            *(const uint2*)&Q16[hoff + (size_t)row * LL + m0 + lc4];
    }
    __syncthreads();

    const int a_krow = (lane & 7) + ((lane >> 4) & 1) * 8;
    const int a_mcol = wm * 32 + ((lane >> 3) & 1) * 8;
    const int b_krow = (lane & 15);
    const int b_mcol = wn * 64 + ((lane >> 4) & 1) * 8;

    float acc[2][8][4];
    #pragma unroll
    for (int mi = 0; mi < 2; mi++)
        #pragma unroll
        for (int ni = 0; ni < 8; ni++)
            #pragma unroll
            for (int q = 0; q < 4; q++) acc[mi][ni][q] = 0.0f;

    #pragma unroll
    for (int ks = 0; ks < 4; ks++) {
        const int kb = ks * 16;
        uint32_t af[2][4], bf[8][2];

        #pragma unroll
        for (int mi = 0; mi < 2; mi++) {
            const uint32_t off =
                (uint32_t)((kb + a_krow) * SPITCH + a_mcol + mi * 16) * 2;
            ldsm_x4_t(af[mi], uK + off);
        }
        #pragma unroll
        for (int nq = 0; nq < 4; nq++) {
            const uint32_t off =
                (uint32_t)((kb + b_krow) * SPITCH + b_mcol + nq * 16) * 2;
            uint32_t th[4];
            ldsm_x4_t(th, uQ + off);
            bf[nq * 2 + 0][0] = th[0]; bf[nq * 2 + 0][1] = th[1];
            bf[nq * 2 + 1][0] = th[2]; bf[nq * 2 + 1][1] = th[3];
        }

        #pragma unroll
        for (int mi = 0; mi < 2; mi++)
            #pragma unroll
            for (int ni = 0; ni < 8; ni++)
                mma_f16(acc[mi][ni], af[mi], bf[ni]);
    }

    const int r = lane >> 2;
    const int g = lane & 3;
    const float scale = 1.0f / 1024.0f;

    #pragma unroll
    for (int mi = 0; mi < 2; mi++) {
        const int l1 = l0 + wm * 32 + mi * 16 + r;
        const int l2 = l1 + 8;
        float rs1 = 0.0f, rs2 = 0.0f;
        #pragma unroll
        for (int ni = 0; ni < 8; ni++) {
            const int m = m0 + wn * 64 + ni * 8 + g * 2;
            const float e0 = __expf(acc[mi][ni][0] * scale);
            const float e1 = __expf(acc[mi][ni][1] * scale);
            const float e2 = __expf(acc[mi][ni][2] * scale);
            const float e3 = __expf(acc[mi][ni][3] * scale);
            *(uint32_t*)&Sb[(size_t)l1 * LL + m] = h2(e0, e1);
            *(uint32_t*)&Sb[(size_t)l2 * LL + m] = h2(e2, e3);
            rs1 += e0 + e1;
            rs2 += e2 + e3;
        }
        rs1 += __shfl_xor_sync(0xffffffffu, rs1, 1);
        rs1 += __shfl_xor_sync(0xffffffffu, rs1, 2);
        rs2 += __shfl_xor_sync(0xffffffffu, rs2, 1);
        rs2 += __shfl_xor_sync(0xffffffffu, rs2, 2);
        if (g == 0) {
            atomicAdd(&Zb[l1], rs1);
            atomicAdd(&Zb[l2], rs2);
        }
    }
}

// ---------------------------------------------------------------------------
// HMMA AV: O = (1/XS_SCALE) * (x*XS_SCALE/Z) @ E.
// scalex folded into loader: reads fp32 x + Z, converts during smem fill.
// ---------------------------------------------------------------------------
#define XP 72
#define PP 136
#define AV_P (64 * XP)
#define AV_SMEM ((64 * XP + 64 * PP) * 2)   // 26,624 B

__global__ __launch_bounds__(256)
void av_mma_kernel(const float* __restrict__ Xf,
                   const float* __restrict__ Z,
                   const __half* __restrict__ Pm,
                   __half* __restrict__ O16)
{
    extern __shared__ __align__(16) __half smem[];
    __half* sX = smem;
    __half* sP = smem + AV_P;
    const uint32_t uX = smem_u32(sX);
    const uint32_t uP = smem_u32(sP);

    const int bh = blockIdx.y;
    const int b = bh >> 4, h = bh & 15;
    const int m0 = blockIdx.x * 128;

    const size_t hoff = (size_t)b * CC * LL + (size_t)h * HD * LL;
    const __half* Ab = Pm + (size_t)bh * LL * LL;
    const float* Zb = Z + (size_t)bh * LL;

    const int tid  = threadIdx.x;
    const int wid  = tid >> 5;
    const int lane = tid & 31;
    const int wm   = wid & 3;
    const int wn   = wid >> 2;

    const int xr  = tid >> 4;          // 0..15
    const int xc4 = (tid & 15) * 4;
    const int prr = tid >> 4;          // 0..15
    const int pc8 = (tid & 15) * 8;

    const int a_row = wm * 16 + (lane & 15);
    const int a_col = ((lane >> 4) & 1) * 8;
    const int b_krow = (lane & 15);
    const int b_mcol = wn * 64 + ((lane >> 4) & 1) * 8;

    float acc[8][4];
    #pragma unroll
    for (int ni = 0; ni < 8; ni++)
        #pragma unroll
        for (int q = 0; q < 4; q++) acc[ni][q] = 0.0f;

    for (int l0 = 0; l0 < LL; l0 += 64) {
        if (l0) __syncthreads();

        // scale factors for this chunk's columns (hoisted; MUFU rcp ×4)
        const float4 zv = *(const float4*)&Zb[l0 + xc4];
        float4 zr;
        zr.x = __fdividef(XS_SCALE, zv.x);
        zr.y = __fdividef(XS_SCALE, zv.y);
        zr.z = __fdividef(XS_SCALE, zv.z);
        zr.w = __fdividef(XS_SCALE, zv.w);

        #pragma unroll
        for (int p = 0; p < 4; p++) {
            const int row = xr + p * 16;      // c
            float4 v = *(const float4*)&Xf[hoff + (size_t)row * LL + l0 + xc4];
            *(uint2*)&sX[row * XP + xc4] =
                make_uint2(h2(v.x * zr.x, v.y * zr.y),
                           h2(v.z * zr.z, v.w * zr.w));
        }
        #pragma unroll
        for (int p = 0; p < 4; p++) {
            const int row = prr + p * 16;     // l within chunk
            *(uint4*)&sP[row * PP + pc8] =
                *(const uint4*)&Ab[(size_t)(l0 + row) * LL + m0 + pc8];
        }
        __syncthreads();

        #pragma unroll
        for (int ks = 0; ks < 4; ks++) {
            const int kb = ks * 16;
            uint32_t af[4], bf[8][2];

            {
                const uint32_t off = (uint32_t)(a_row * XP + kb + a_col) * 2;
                ldsm_x4(af, uX + off);
            }
            #pragma unroll
            for (int nq = 0; nq < 4; nq++) {
                const uint32_t off =
                    (uint32_t)((kb + b_krow) * PP + b_mcol + nq * 16) * 2;
                uint32_t th[4];
                ldsm_x4_t(th, uP + off);
                bf[nq * 2 + 0][0] = th[0]; bf[nq * 2 + 0][1] = th[1];
                bf[nq * 2 + 1][0] = th[2]; bf[nq * 2 + 1][1] = th[3];
            }

            #pragma unroll
            for (int ni = 0; ni < 8; ni++)
                mma_f16(acc[ni], af, bf[ni]);
        }
    }

    const int r = lane >> 2;
    const int g = lane & 3;
    const int c1 = wm * 16 + r;
    const int c2 = c1 + 8;
    const float inv = 1.0f / XS_SCALE;

    #pragma unroll
    for (int ni = 0; ni < 8; ni++) {
        const int m = m0 + wn * 64 + ni * 8 + g * 2;
        const size_t i1 = hoff + (size_t)c1 * LL + m;
        const size_t i2 = hoff + (size_t)c2 * LL + m;
        *(uint32_t*)&O16[i1] = h2(acc[ni][0] * inv, acc[ni][1] * inv);
        *(uint32_t*)&O16[i2] = h2(acc[ni][2] * inv, acc[ni][3] * inv);
    }
}

// ---------------------------------------------------------------------------
extern "C" void kernel_launch(void* const* d_in, const int* in_sizes, int n_in,
                              void* d_out, int out_size)
{
    const float* x   = (const float*)d_in[0];
    const float* kw  = (const float*)d_in[1];
    const float* kb  = (const float*)d_in[2];
    const float* qw  = (const float*)d_in[3];
    const float* qb  = (const float*)d_in[4];
    const float* pw  = (const float*)d_in[5];
    const float* pb  = (const float*)d_in[6];
    const float* c1w = (const float*)d_in[7];
    const float* c1b = (const float*)d_in[8];
    const float* c2w = (const float*)d_in[9];
    const float* c2b = (const float*)d_in[10];
    float* out = (float*)d_out;

    __half *gX16,*gK16,*gQ16,*gA16,*gY16,*gT16,*gS,*gW16;
    float *gY, *gZ;
    cudaGetSymbolAddress((void**)&gX16,  g_X16);
    cudaGetSymbolAddress((void**)&gK16,  g_K16);
    cudaGetSymbolAddress((void**)&gQ16,  g_Q16);
    cudaGetSymbolAddress((void**)&gA16,  g_A16);
    cudaGetSymbolAddress((void**)&gY16,  g_Y16);
    cudaGetSymbolAddress((void**)&gT16,  g_T16);
    cudaGetSymbolAddress((void**)&gS,    g_S);
    cudaGetSymbolAddress((void**)&gW16,  g_W16);
    cudaGetSymbolAddress((void**)&gY,    g_Y);
    cudaGetSymbolAddress((void**)&gZ,    g_Z);

    static bool attr_done = false;
    if (!attr_done) {
        cudaFuncSetAttribute(scores_mma_kernel,
                             cudaFuncAttributeMaxDynamicSharedMemorySize, SCORES_SMEM);
        cudaFuncSetAttribute(av_mma_kernel,
                             cudaFuncAttributeMaxDynamicSharedMemorySize, AV_SMEM);
        cudaFuncSetAttribute(conv_mma_kernel<true,  false, 0, 0>,
                             cudaFuncAttributeMaxDynamicSharedMemorySize, CONV_SMEM);
        cudaFuncSetAttribute(conv_mma_kernel<false, false, 1, 1>,
                             cudaFuncAttributeMaxDynamicSharedMemorySize, CONV_SMEM);
        cudaFuncSetAttribute(conv_mma_kernel<false, true,  0, 0>,
                             cudaFuncAttributeMaxDynamicSharedMemorySize, CONV_SMEM);
        cudaFuncSetAttribute(conv_mma_kernel<false, false, 2, 2>,
                             cudaFuncAttributeMaxDynamicSharedMemorySize, CONV_SMEM);
        attr_done = true;
    }

    // fused prep: x->fp16, 5 weights->fp16, Z=0
    prep_kernel<<<PREP_BLOCKS, 256>>>(x, kw, qw, pw, c1w, c2w, gX16, gW16, gZ);

    // K and Q projections in ONE launch over the stacked [2048,1024] weight
    conv_mma_kernel<true, false, 0, 0><<<dim3(LL / 128, 2 * CC / 128, BB), 128, CONV_SMEM>>>(
        gW16, kb, qb, gX16, nullptr, gK16, gQ16, nullptr, nullptr);

    // scores -> E + row sums Z ; AV (scalex folded into its loader)
    scores_mma_kernel<<<dim3(LL / 128, LL / 128, NBH), 256, SCORES_SMEM>>>(
        gK16, gQ16, gS, gZ);
    av_mma_kernel<<<dim3(LL / 128, NBH), 256, AV_SMEM>>>(x, gZ, gS, gA16);

    // y = pconv(AO) + x   (fp32 for residual + fp16 for c1)
    conv_mma_kernel<false, false, 1, 1><<<dim3(LL / 128, CC / 128, BB), 128, CONV_SMEM>>>(
        gW16 + 2 * WELEMS, pb, nullptr, gA16, gY, gY16, nullptr, x, nullptr);
    // t = relu(c1(y)) -> fp16
    conv_mma_kernel<false, true, 0, 0><<<dim3(LL / 128, CC / 128, BB), 128, CONV_SMEM>>>(
        gW16 + 3 * WELEMS, c1b, nullptr, gY16, nullptr, gT16, nullptr, nullptr, nullptr);
    // out = c2(t) + y + x  (fp32 only)
    conv_mma_kernel<false, false, 2, 2><<<dim3(LL / 128, CC / 128, BB), 128, CONV_SMEM>>>(
        gW16 + 4 * WELEMS, c2b, nullptr, gT16, out, nullptr, nullptr, gY, x);
}

// round 16
// speedup vs baseline: 1.0706x; 1.0706x over previous
#include <cuda_runtime.h>
#include <cuda_fp16.h>
#include <cstdint>

// Problem constants
#define BB 2
#define CC 1024
#define LL 2048
#define HH 16
#define HD 64
#define BCL (BB*CC*LL)               // 4,194,304 elems
#define NBH (BB*HH)                  // 32
#define SROWS ((size_t)NBH * LL)     // 65536
#define SELEMS (SROWS * LL)          // 134,217,728 elems (256 MB fp16)
#define WELEMS (CC*CC)               // 1,048,576 per weight
#define XS_SCALE 256.0f              // pre-scale for x/Z (avoid fp16 subnormals)

// Scratch (device globals — runtime allocation is forbidden)
__device__ __half g_X16 [BCL];          // x fp16
__device__ __half g_K16 [BCL];          // K proj fp16
__device__ __half g_Q16 [BCL];          // Q proj fp16
__device__ __half g_A16 [BCL];          // attn out fp16
__device__ float  g_Y   [BCL];          // y fp32 (residual)
__device__ __half g_Y16 [BCL];          // y fp16
__device__ __half g_T16 [BCL];          // relu(c1(y)) fp16
__device__ __half g_S   [SELEMS];       // E = exp(scores) fp16
__device__ float  g_Z   [SROWS];        // row sums of E
__device__ __half g_W16 [5*WELEMS];     // weights fp16 (kw,qw,pw,c1w,c2w)

// ---------------------------------------------------------------------------
// helpers
// ---------------------------------------------------------------------------
__device__ __forceinline__ uint32_t smem_u32(const void* p) {
    uint32_t a;
    asm("{ .reg .u64 t; cvta.to.shared.u64 t, %1; cvt.u32.u64 %0, t; }"
        : "=r"(a) : "l"(p));
    return a;
}
__device__ __forceinline__ uint32_t h2(float a, float b) {
    __half2 t = __floats2half2_rn(a, b);
    return *reinterpret_cast<uint32_t*>(&t);
}

__device__ __forceinline__ void ldsm_x4(uint32_t r[4], uint32_t addr) {
    asm volatile("ldmatrix.sync.aligned.m8n8.x4.shared.b16 {%0,%1,%2,%3}, [%4];"
                 : "=r"(r[0]), "=r"(r[1]), "=r"(r[2]), "=r"(r[3]) : "r"(addr));
}
__device__ __forceinline__ void ldsm_x4_t(uint32_t r[4], uint32_t addr) {
    asm volatile("ldmatrix.sync.aligned.m8n8.x4.trans.shared.b16 {%0,%1,%2,%3}, [%4];"
                 : "=r"(r[0]), "=r"(r[1]), "=r"(r[2]), "=r"(r[3]) : "r"(addr));
}
__device__ __forceinline__ void mma_f16(float c[4], const uint32_t a[4],
                                        const uint32_t b[2]) {
    asm volatile("mma.sync.aligned.m16n8k16.row.col.f32.f16.f16.f32 "
                 "{%0,%1,%2,%3}, {%4,%5,%6,%7}, {%8,%9}, {%0,%1,%2,%3};"
                 : "+f"(c[0]), "+f"(c[1]), "+f"(c[2]), "+f"(c[3])
                 : "r"(a[0]), "r"(a[1]), "r"(a[2]), "r"(a[3]),
                   "r"(b[0]), "r"(b[1]));
}

// ---------------------------------------------------------------------------
// fused prep: cvt x, cvt 5 weights, zero Z. One launch.
// ---------------------------------------------------------------------------
#define XBLK (BCL/4/256)            // 4096
#define WBLK (WELEMS/4/256)         // 1024
#define ZBLK (SROWS/4/256)          // 64
#define PREP_BLOCKS (XBLK + 5*WBLK + ZBLK)   // 9280

__global__ __launch_bounds__(256)
void prep_kernel(const float* __restrict__ x,
                 const float* __restrict__ kw, const float* __restrict__ qw,
                 const float* __restrict__ pw, const float* __restrict__ c1w,
                 const float* __restrict__ c2w,
                 __half* __restrict__ X16, __half* __restrict__ W16,
                 float* __restrict__ Z)
{
    const int blk = blockIdx.x;
    if (blk < XBLK) {
        const unsigned i = blk * 256u + threadIdx.x;
        float4 v = reinterpret_cast<const float4*>(x)[i];
        reinterpret_cast<uint2*>(X16)[i] = make_uint2(h2(v.x, v.y), h2(v.z, v.w));
    } else if (blk < XBLK + 5 * WBLK) {
        const int wi = (blk - XBLK) / WBLK;
        const int wb = (blk - XBLK) % WBLK;
        const float* src = (wi == 0) ? kw : (wi == 1) ? qw : (wi == 2) ? pw
                          : (wi == 3) ? c1w : c2w;
        const unsigned i = wb * 256u + threadIdx.x;
        float4 v = reinterpret_cast<const float4*>(src)[i];
        reinterpret_cast<uint2*>(W16 + (size_t)wi * WELEMS)[i] =
            make_uint2(h2(v.x, v.y), h2(v.z, v.w));
    } else {
        const unsigned i = (blk - XBLK - 5 * WBLK) * 256u + threadIdx.x;
        reinterpret_cast<float4*>(Z)[i] = make_float4(0.f, 0.f, 0.f, 0.f);
    }
}

// ---------------------------------------------------------------------------
// HMMA conv1x1, fp16 operands, fp32 accumulate (R13-verified: 256 thr,
// 8 warps, warp tile 32x64, block 128x128, K chunks of 64).
// KQ=true: stacked [2C, C] weight (kw‖qw); o0 >= CC -> Q16/qb.
// OMODE: 0 = fp16 O16 only; 1 = fp32 Out AND fp16 O16; 2 = fp32 only.
// ---------------------------------------------------------------------------
#define APITCH 72
#define BPITCH 136
#define SM_B (128 * APITCH)
#define CONV_SMEM ((128 * APITCH + 64 * BPITCH) * 2)   // 35,840 B

template<bool KQ, bool RELU, int NADD, int OMODE>
__global__ __launch_bounds__(256)
void conv_mma_kernel(const __half* __restrict__ W16,
                     const float* __restrict__ bias,
                     const float* __restrict__ bias2,
                     const __half* __restrict__ B16,
                     float* __restrict__ Out,
                     __half* __restrict__ O16,
                     __half* __restrict__ O16b,
                     const float* __restrict__ A1,
                     const float* __restrict__ A2)
{
    extern __shared__ __align__(16) __half smem[];
    __half* sA = smem;
    __half* sB = smem + SM_B;
    const uint32_t uA = smem_u32(sA);
    const uint32_t uB = smem_u32(sB);

    const int b  = blockIdx.z;
    int o0 = blockIdx.y * 128;
    const int l0 = blockIdx.x * 128;
    const size_t boff = (size_t)b * CC * LL;

    const float* biasp = bias;
    __half* O16p = O16;
    const int wrow0 = o0;
    if (KQ && o0 >= CC) {
        biasp = bias2;
        O16p = O16b;
        o0 -= CC;
    }

    const int tid  = threadIdx.x;
    const int wid  = tid >> 5;
    const int lane = tid & 31;
    const int wm   = wid & 3;
    const int wn   = wid >> 2;

    const int ar  = tid >> 4;          // A loader: row group 0..15
    const int ac4 = (tid & 15) * 4;
    const int bc  = tid >> 5;          // B loader: row group 0..7
    const int bl4 = (tid & 31) * 4;

    const int a_row = wm * 32 + (lane & 15);
    const int a_col = ((lane >> 4) & 1) * 8;
    const int b_row = (lane & 15);
    const int b_colb = wn * 64 + ((lane >> 4) & 1) * 8;

    float acc[2][8][4];
    #pragma unroll
    for (int mi = 0; mi < 2; mi++)
        #pragma unroll
        for (int ni = 0; ni < 8; ni++)
            #pragma unroll
            for (int q = 0; q < 4; q++) acc[mi][ni][q] = 0.0f;

    for (int ci = 0; ci < CC / 64; ci++) {
        const int c0 = ci * 64;
        if (ci) __syncthreads();

        #pragma unroll
        for (int p = 0; p < 8; p++) {
            const int row = ar + p * 16;
            *(uint2*)&sA[row * APITCH + ac4] =
                *(const uint2*)&W16[(size_t)(wrow0 + row) * CC + c0 + ac4];
        }
        #pragma unroll
        for (int p = 0; p < 8; p++) {
            const int row = bc + p * 8;
            *(uint2*)&sB[row * BPITCH + bl4] =
                *(const uint2*)&B16[boff + (size_t)(c0 + row) * LL + l0 + bl4];
        }
        __syncthreads();

        #pragma unroll
        for (int ks = 0; ks < 4; ks++) {
            const int kb = ks * 16;
            uint32_t af[2][4], bf[8][2];

            #pragma unroll
            for (int mi = 0; mi < 2; mi++) {
                const uint32_t off =
                    (uint32_t)((a_row + mi * 16) * APITCH + kb + a_col) * 2;
                ldsm_x4(af[mi], uA + off);
            }
            #pragma unroll
            for (int nq = 0; nq < 4; nq++) {
                const uint32_t off =
                    (uint32_t)((kb + b_row) * BPITCH + b_colb + nq * 16) * 2;
                uint32_t th[4];
                ldsm_x4_t(th, uB + off);
                bf[nq * 2 + 0][0] = th[0]; bf[nq * 2 + 0][1] = th[1];
                bf[nq * 2 + 1][0] = th[2]; bf[nq * 2 + 1][1] = th[3];
            }

            #pragma unroll
            for (int mi = 0; mi < 2; mi++)
                #pragma unroll
                for (int ni = 0; ni < 8; ni++)
                    mma_f16(acc[mi][ni], af[mi], bf[ni]);
        }
    }

    const int r = lane >> 2;
    const int g = lane & 3;

    #pragma unroll
    for (int mi = 0; mi < 2; mi++) {
        const int o1 = o0 + wm * 32 + mi * 16 + r;
        const int o2 = o1 + 8;
        const float bv1 = __ldg(&biasp[o1]);
        const float bv2 = __ldg(&biasp[o2]);
        #pragma unroll
        for (int ni = 0; ni < 8; ni++) {
            const int l = l0 + wn * 64 + ni * 8 + g * 2;
            float2 v01 = make_float2(acc[mi][ni][0] + bv1, acc[mi][ni][1] + bv1);
            float2 v23 = make_float2(acc[mi][ni][2] + bv2, acc[mi][ni][3] + bv2);
            if (RELU) {
                v01.x = fmaxf(v01.x, 0.f); v01.y = fmaxf(v01.y, 0.f);
                v23.x = fmaxf(v23.x, 0.f); v23.y = fmaxf(v23.y, 0.f);
            }
            const size_t i1 = boff + (size_t)o1 * LL + l;
            const size_t i2 = boff + (size_t)o2 * LL + l;
            if (NADD >= 1) {
                float2 a1v = *(const float2*)&A1[i1];
                float2 a2v = *(const float2*)&A1[i2];
                v01.x += a1v.x; v01.y += a1v.y;
                v23.x += a2v.x; v23.y += a2v.y;
            }
            if (NADD >= 2) {
                float2 a1v = *(const float2*)&A2[i1];
                float2 a2v = *(const float2*)&A2[i2];
                v01.x += a1v.x; v01.y += a1v.y;
                v23.x += a2v.x; v23.y += a2v.y;
            }
            if (OMODE >= 1) {
                *(float2*)&Out[i1] = v01;
                *(float2*)&Out[i2] = v23;
            }
            if (OMODE <= 1) {
                *(uint32_t*)&O16p[i1] = h2(v01.x, v01.y);
                *(uint32_t*)&O16p[i2] = h2(v23.x, v23.y);
            }
        }
    }
}

// ---------------------------------------------------------------------------
// HMMA scores -> E = exp(scores/1024) (fp16) + per-row sums Z (atomicAdd).
// (R11/R13-verified, unchanged.)
// ---------------------------------------------------------------------------
#define SPITCH 136
#define SC_Q (64 * SPITCH)
#define SCORES_SMEM (2 * 64 * SPITCH * 2)   // 34,816 B

__global__ __launch_bounds__(256)
void scores_mma_kernel(const __half* __restrict__ K16,
                       const __half* __restrict__ Q16,
                       __half* __restrict__ S,
                       float* __restrict__ Z)
{
    extern __shared__ __align__(16) __half smem[];
    __half* sK = smem;
    __half* sQ = smem + SC_Q;
    const uint32_t uK = smem_u32(sK);
    const uint32_t uQ = smem_u32(sQ);

    const int bh = blockIdx.z;
    const int b = bh >> 4, h = bh & 15;
    const int l0 = blockIdx.y * 128;
    const int m0 = blockIdx.x * 128;

    const size_t hoff = (size_t)b * CC * LL + (size_t)h * HD * LL;
    __half* Sb = S + (size_t)bh * LL * LL;
    float* Zb = Z + (size_t)bh * LL;

    const int tid  = threadIdx.x;
    const int wid  = tid >> 5;
    const int lane = tid & 31;
    const int wm   = wid & 3;
    const int wn   = wid >> 2;

    const int lr  = tid >> 5;
    const int lc4 = (tid & 31) * 4;

    #pragma unroll
    for (int p = 0; p < 8; p++) {
        const int row = lr + p * 8;
        *(uint2*)&sK[row * SPITCH + lc4] =
            *(const uint2*)&K16[hoff + (size_t)row * LL + l0 + lc4];
        *(uint2*)&sQ[row * SPITCH + lc4] =
            *(const uint2*)&Q16[hoff + (size_t)row * LL + m0 + lc4];
    }
    __syncthreads();

    const int a_krow = (lane & 7) + ((lane >> 4) & 1) * 8;
    const int a_mcol = wm * 32 + ((lane >> 3) & 1) * 8;
    const int b_krow = (lane & 15);
    const int b_mcol = wn * 64 + ((lane >> 4) & 1) * 8;

    float acc[2][8][4];
    #pragma unroll
    for (int mi = 0; mi < 2; mi++)
        #pragma unroll
        for (int ni = 0; ni < 8; ni++)
            #pragma unroll
            for (int q = 0; q < 4; q++) acc[mi][ni][q] = 0.0f;

    #pragma unroll
    for (int ks = 0; ks < 4; ks++) {
        const int kb = ks * 16;
        uint32_t af[2][4], bf[8][2];

        #pragma unroll
        for (int mi = 0; mi < 2; mi++) {
            const uint32_t off =
                (uint32_t)((kb + a_krow) * SPITCH + a_mcol + mi * 16) * 2;
            ldsm_x4_t(af[mi], uK + off);
        }
        #pragma unroll
        for (int nq = 0; nq < 4; nq++) {
            const uint32_t off =
                (uint32_t)((kb + b_krow) * SPITCH + b_mcol + nq * 16) * 2;
            uint32_t th[4];
            ldsm_x4_t(th, uQ + off);
            bf[nq * 2 + 0][0] = th[0]; bf[nq * 2 + 0][1] = th[1];
            bf[nq * 2 + 1][0] = th[2]; bf[nq * 2 + 1][1] = th[3];
        }

        #pragma unroll
        for (int mi = 0; mi < 2; mi++)
            #pragma unroll
            for (int ni = 0; ni < 8; ni++)
                mma_f16(acc[mi][ni], af[mi], bf[ni]);
    }

    const int r = lane >> 2;
    const int g = lane & 3;
    const float scale = 1.0f / 1024.0f;

    #pragma unroll
    for (int mi = 0; mi < 2; mi++) {
        const int l1 = l0 + wm * 32 + mi * 16 + r;
        const int l2 = l1 + 8;
        float rs1 = 0.0f, rs2 = 0.0f;
        #pragma unroll
        for (int ni = 0; ni < 8; ni++) {
            const int m = m0 + wn * 64 + ni * 8 + g * 2;
            const float e0 = __expf(acc[mi][ni][0] * scale);
            const float e1 = __expf(acc[mi][ni][1] * scale);
            const float e2 = __expf(acc[mi][ni][2] * scale);
            const float e3 = __expf(acc[mi][ni][3] * scale);
            *(uint32_t*)&Sb[(size_t)l1 * LL + m] = h2(e0, e1);
            *(uint32_t*)&Sb[(size_t)l2 * LL + m] = h2(e2, e3);
            rs1 += e0 + e1;
            rs2 += e2 + e3;
        }
        rs1 += __shfl_xor_sync(0xffffffffu, rs1, 1);
        rs1 += __shfl_xor_sync(0xffffffffu, rs1, 2);
        rs2 += __shfl_xor_sync(0xffffffffu, rs2, 1);
        rs2 += __shfl_xor_sync(0xffffffffu, rs2, 2);
        if (g == 0) {
            atomicAdd(&Zb[l1], rs1);
            atomicAdd(&Zb[l2], rs2);
        }
    }
}

// ---------------------------------------------------------------------------
// HMMA AV: O = (1/XS_SCALE) * (x*XS_SCALE/Z) @ E.
// scalex folded into loader (R14-measured neutral, deletes a kernel).
// 256 threads, 8 warps, warp tile 16x64 (R11/R13 shape).
// ---------------------------------------------------------------------------
#define XP 72
#define PP 136
#define AV_P (64 * XP)
#define AV_SMEM ((64 * XP + 64 * PP) * 2)   // 26,624 B

__global__ __launch_bounds__(256)
void av_mma_kernel(const float* __restrict__ Xf,
                   const float* __restrict__ Z,
                   const __half* __restrict__ Pm,
                   __half* __restrict__ O16)
{
    extern __shared__ __align__(16) __half smem[];
    __half* sX = smem;
    __half* sP = smem + AV_P;
    const uint32_t uX = smem_u32(sX);
    const uint32_t uP = smem_u32(sP);

    const int bh = blockIdx.y;
    const int b = bh >> 4, h = bh & 15;
    const int m0 = blockIdx.x * 128;

    const size_t hoff = (size_t)b * CC * LL + (size_t)h * HD * LL;
    const __half* Ab = Pm + (size_t)bh * LL * LL;
    const float* Zb = Z + (size_t)bh * LL;

    const int tid  = threadIdx.x;
    const int wid  = tid >> 5;
    const int lane = tid & 31;
    const int wm   = wid & 3;
    const int wn   = wid >> 2;

    const int xr  = tid >> 4;          // 0..15
    const int xc4 = (tid & 15) * 4;
    const int prr = tid >> 4;          // 0..15
    const int pc8 = (tid & 15) * 8;

    const int a_row = wm * 16 + (lane & 15);
    const int a_col = ((lane >> 4) & 1) * 8;
    const int b_krow = (lane & 15);
    const int b_mcol = wn * 64 + ((lane >> 4) & 1) * 8;

    float acc[8][4];
    #pragma unroll
    for (int ni = 0; ni < 8; ni++)
        #pragma unroll
        for (int q = 0; q < 4; q++) acc[ni][q] = 0.0f;

    for (int l0 = 0; l0 < LL; l0 += 64) {
        if (l0) __syncthreads();

        // per-column scale factors for this chunk (4 rcp per thread)
        const float4 zv = *(const float4*)&Zb[l0 + xc4];
        float4 zr;
        zr.x = __fdividef(XS_SCALE, zv.x);
        zr.y = __fdividef(XS_SCALE, zv.y);
        zr.z = __fdividef(XS_SCALE, zv.z);
        zr.w = __fdividef(XS_SCALE, zv.w);

        #pragma unroll
        for (int p = 0; p < 4; p++) {
            const int row = xr + p * 16;      // c
            float4 v = *(const float4*)&Xf[hoff + (size_t)row * LL + l0 + xc4];
            *(uint2*)&sX[row * XP + xc4] =
                make_uint2(h2(v.x * zr.x, v.y * zr.y),
                           h2(v.z * zr.z, v.w * zr.w));
        }
        #pragma unroll
        for (int p = 0; p < 4; p++) {
            const int row = prr + p * 16;     // l within chunk
            *(uint4*)&sP[row * PP + pc8] =
                *(const uint4*)&Ab[(size_t)(l0 + row) * LL + m0 + pc8];
        }
        __syncthreads();

        #pragma unroll
        for (int ks = 0; ks < 4; ks++) {
            const int kb = ks * 16;
            uint32_t af[4], bf[8][2];

            {
                const uint32_t off = (uint32_t)(a_row * XP + kb + a_col) * 2;
                ldsm_x4(af, uX + off);
            }
            #pragma unroll
            for (int nq = 0; nq < 4; nq++) {
                const uint32_t off =
                    (uint32_t)((kb + b_krow) * PP + b_mcol + nq * 16) * 2;
                uint32_t th[4];
                ldsm_x4_t(th, uP + off);
                bf[nq * 2 + 0][0] = th[0]; bf[nq * 2 + 0][1] = th[1];
                bf[nq * 2 + 1][0] = th[2]; bf[nq * 2 + 1][1] = th[3];
            }

            #pragma unroll
            for (int ni = 0; ni < 8; ni++)
                mma_f16(acc[ni], af, bf[ni]);
        }
    }

    const int r = lane >> 2;
    const int g = lane & 3;
    const int c1 = wm * 16 + r;
    const int c2 = c1 + 8;
    const float inv = 1.0f / XS_SCALE;

    #pragma unroll
    for (int ni = 0; ni < 8; ni++) {
        const int m = m0 + wn * 64 + ni * 8 + g * 2;
        const size_t i1 = hoff + (size_t)c1 * LL + m;
        const size_t i2 = hoff + (size_t)c2 * LL + m;
        *(uint32_t*)&O16[i1] = h2(acc[ni][0] * inv, acc[ni][1] * inv);
        *(uint32_t*)&O16[i2] = h2(acc[ni][2] * inv, acc[ni][3] * inv);
    }
}

// ---------------------------------------------------------------------------
extern "C" void kernel_launch(void* const* d_in, const int* in_sizes, int n_in,
                              void* d_out, int out_size)
{
    const float* x   = (const float*)d_in[0];
    const float* kw  = (const float*)d_in[1];
    const float* kb  = (const float*)d_in[2];
    const float* qw  = (const float*)d_in[3];
    const float* qb  = (const float*)d_in[4];
    const float* pw  = (const float*)d_in[5];
    const float* pb  = (const float*)d_in[6];
    const float* c1w = (const float*)d_in[7];
    const float* c1b = (const float*)d_in[8];
    const float* c2w = (const float*)d_in[9];
    const float* c2b = (const float*)d_in[10];
    float* out = (float*)d_out;

    __half *gX16,*gK16,*gQ16,*gA16,*gY16,*gT16,*gS,*gW16;
    float *gY, *gZ;
    cudaGetSymbolAddress((void**)&gX16,  g_X16);
    cudaGetSymbolAddress((void**)&gK16,  g_K16);
    cudaGetSymbolAddress((void**)&gQ16,  g_Q16);
    cudaGetSymbolAddress((void**)&gA16,  g_A16);
    cudaGetSymbolAddress((void**)&gY16,  g_Y16);
    cudaGetSymbolAddress((void**)&gT16,  g_T16);
    cudaGetSymbolAddress((void**)&gS,    g_S);
    cudaGetSymbolAddress((void**)&gW16,  g_W16);
    cudaGetSymbolAddress((void**)&gY,    g_Y);
    cudaGetSymbolAddress((void**)&gZ,    g_Z);

    static bool attr_done = false;
    if (!attr_done) {
        cudaFuncSetAttribute(scores_mma_kernel,
                             cudaFuncAttributeMaxDynamicSharedMemorySize, SCORES_SMEM);
        cudaFuncSetAttribute(av_mma_kernel,
                             cudaFuncAttributeMaxDynamicSharedMemorySize, AV_SMEM);
        cudaFuncSetAttribute(conv_mma_kernel<true,  false, 0, 0>,
                             cudaFuncAttributeMaxDynamicSharedMemorySize, CONV_SMEM);
        cudaFuncSetAttribute(conv_mma_kernel<false, false, 1, 1>,
                             cudaFuncAttributeMaxDynamicSharedMemorySize, CONV_SMEM);
        cudaFuncSetAttribute(conv_mma_kernel<false, true,  0, 0>,
                             cudaFuncAttributeMaxDynamicSharedMemorySize, CONV_SMEM);
        cudaFuncSetAttribute(conv_mma_kernel<false, false, 2, 2>,
                             cudaFuncAttributeMaxDynamicSharedMemorySize, CONV_SMEM);
        attr_done = true;
    }

    // fused prep: x->fp16, 5 weights->fp16, Z=0
    prep_kernel<<<PREP_BLOCKS, 256>>>(x, kw, qw, pw, c1w, c2w, gX16, gW16, gZ);

    // K and Q projections in ONE launch over the stacked [2048,1024] weight
    conv_mma_kernel<true, false, 0, 0><<<dim3(LL / 128, 2 * CC / 128, BB), 256, CONV_SMEM>>>(
        gW16, kb, qb, gX16, nullptr, gK16, gQ16, nullptr, nullptr);

    // scores -> E + row sums Z ; AV (scalex folded into its loader)
    scores_mma_kernel<<<dim3(LL / 128, LL / 128, NBH), 256, SCORES_SMEM>>>(
        gK16, gQ16, gS, gZ);
    av_mma_kernel<<<dim3(LL / 128, NBH), 256, AV_SMEM>>>(x, gZ, gS, gA16);

    // y = pconv(AO) + x   (fp32 for residual + fp16 for c1)
    conv_mma_kernel<false, false, 1, 1><<<dim3(LL / 128, CC / 128, BB), 256, CONV_SMEM>>>(
        gW16 + 2 * WELEMS, pb, nullptr, gA16, gY, gY16, nullptr, x, nullptr);
    // t = relu(c1(y)) -> fp16
    conv_mma_kernel<false, true, 0, 0><<<dim3(LL / 128, CC / 128, BB), 256, CONV_SMEM>>>(
        gW16 + 3 * WELEMS, c1b, nullptr, gY16, nullptr, gT16, nullptr, nullptr, nullptr);
    // out = c2(t) + y + x  (fp32 only)
    conv_mma_kernel<false, false, 2, 2><<<dim3(LL / 128, CC / 128, BB), 256, CONV_SMEM>>>(
        gW16 + 4 * WELEMS, c2b, nullptr, gT16, out, nullptr, nullptr, gY, x);
}

// round 17
// speedup vs baseline: 1.2380x; 1.1564x over previous
#include <cuda_runtime.h>
#include <cuda_fp16.h>
#include <cstdint>

// Problem constants
#define BB 2
#define CC 1024
#define LL 2048
#define HH 16
#define HD 64
#define BCL (BB*CC*LL)               // 4,194,304 elems
#define NBH (BB*HH)                  // 32
#define SROWS ((size_t)NBH * LL)     // 65536
#define SELEMS (SROWS * LL)          // 134,217,728 elems (256 MB fp16)
#define WELEMS (CC*CC)               // 1,048,576 per weight
#define XS_SCALE 256.0f              // pre-scale for x/Z (avoid fp16 subnormals)

// Scratch (device globals — runtime allocation is forbidden)
__device__ __half g_X16 [BCL];          // x fp16
__device__ __half g_XS16[BCL];          // x * XS_SCALE / Z fp16 (AV input)
__device__ __half g_K16 [BCL];          // K proj fp16
__device__ __half g_Q16 [BCL];          // Q proj fp16
__device__ __half g_A16 [BCL];          // attn out fp16
__device__ float  g_Y   [BCL];          // y fp32 (residual)
__device__ __half g_Y16 [BCL];          // y fp16
__device__ __half g_T16 [BCL];          // relu(c1(y)) fp16
__device__ __half g_S   [SELEMS];       // E = exp(scores) fp16
__device__ float  g_Z   [SROWS];        // row sums of E
__device__ __half g_W16 [5*WELEMS];     // weights fp16 (kw,qw,pw,c1w,c2w)

// ---------------------------------------------------------------------------
// helpers
// ---------------------------------------------------------------------------
__device__ __forceinline__ uint32_t smem_u32(const void* p) {
    uint32_t a;
    asm("{ .reg .u64 t; cvta.to.shared.u64 t, %1; cvt.u32.u64 %0, t; }"
        : "=r"(a) : "l"(p));
    return a;
}
__device__ __forceinline__ uint32_t h2(float a, float b) {
    __half2 t = __floats2half2_rn(a, b);
    return *reinterpret_cast<uint32_t*>(&t);
}

__device__ __forceinline__ void ldsm_x4(uint32_t r[4], uint32_t addr) {
    asm volatile("ldmatrix.sync.aligned.m8n8.x4.shared.b16 {%0,%1,%2,%3}, [%4];"
                 : "=r"(r[0]), "=r"(r[1]), "=r"(r[2]), "=r"(r[3]) : "r"(addr));
}
__device__ __forceinline__ void ldsm_x4_t(uint32_t r[4], uint32_t addr) {
    asm volatile("ldmatrix.sync.aligned.m8n8.x4.trans.shared.b16 {%0,%1,%2,%3}, [%4];"
                 : "=r"(r[0]), "=r"(r[1]), "=r"(r[2]), "=r"(r[3]) : "r"(addr));
}
__device__ __forceinline__ void mma_f16(float c[4], const uint32_t a[4],
                                        const uint32_t b[2]) {
    asm volatile("mma.sync.aligned.m16n8k16.row.col.f32.f16.f16.f32 "
                 "{%0,%1,%2,%3}, {%4,%5,%6,%7}, {%8,%9}, {%0,%1,%2,%3};"
                 : "+f"(c[0]), "+f"(c[1]), "+f"(c[2]), "+f"(c[3])
                 : "r"(a[0]), "r"(a[1]), "r"(a[2]), "r"(a[3]),
                   "r"(b[0]), "r"(b[1]));
}

// ---------------------------------------------------------------------------
// fused prep: cvt x, cvt 5 weights, zero Z. One launch.
// ---------------------------------------------------------------------------
#define XBLK (BCL/4/256)            // 4096
#define WBLK (WELEMS/4/256)         // 1024
#define ZBLK (SROWS/4/256)          // 64
#define PREP_BLOCKS (XBLK + 5*WBLK + ZBLK)   // 9280

__global__ __launch_bounds__(256)
void prep_kernel(const float* __restrict__ x,
                 const float* __restrict__ kw, const float* __restrict__ qw,
                 const float* __restrict__ pw, const float* __restrict__ c1w,
                 const float* __restrict__ c2w,
                 __half* __restrict__ X16, __half* __restrict__ W16,
                 float* __restrict__ Z)
{
    const int blk = blockIdx.x;
    if (blk < XBLK) {
        const unsigned i = blk * 256u + threadIdx.x;
        float4 v = reinterpret_cast<const float4*>(x)[i];
        reinterpret_cast<uint2*>(X16)[i] = make_uint2(h2(v.x, v.y), h2(v.z, v.w));
    } else if (blk < XBLK + 5 * WBLK) {
        const int wi = (blk - XBLK) / WBLK;
        const int wb = (blk - XBLK) % WBLK;
        const float* src = (wi == 0) ? kw : (wi == 1) ? qw : (wi == 2) ? pw
                          : (wi == 3) ? c1w : c2w;
        const unsigned i = wb * 256u + threadIdx.x;
        float4 v = reinterpret_cast<const float4*>(src)[i];
        reinterpret_cast<uint2*>(W16 + (size_t)wi * WELEMS)[i] =
            make_uint2(h2(v.x, v.y), h2(v.z, v.w));
    } else {
        const unsigned i = (blk - XBLK - 5 * WBLK) * 256u + threadIdx.x;
        reinterpret_cast<float4*>(Z)[i] = make_float4(0.f, 0.f, 0.f, 0.f);
    }
}

// XS = x * XS_SCALE / Z[bh,l], fp16  (R13-verified standalone kernel)
__global__ __launch_bounds__(256)
void scalex_kernel(const float* __restrict__ x, const float* __restrict__ Z,
                   __half* __restrict__ out)
{
    const unsigned i = blockIdx.x * 256u + threadIdx.x;
    const unsigned e0 = i * 4;
    const unsigned l  = e0 % LL;
    const unsigned c  = (e0 / LL) % CC;
    const unsigned b  = e0 / (CC * LL);
    const unsigned bh = b * HH + (c >> 6);

    float4 v = reinterpret_cast<const float4*>(x)[i];
    float4 z = *reinterpret_cast<const float4*>(&Z[(size_t)bh * LL + l]);
    v.x = __fdividef(v.x * XS_SCALE, z.x);
    v.y = __fdividef(v.y * XS_SCALE, z.y);
    v.z = __fdividef(v.z * XS_SCALE, z.z);
    v.w = __fdividef(v.w * XS_SCALE, z.w);
    reinterpret_cast<uint2*>(out)[i] = make_uint2(h2(v.x, v.y), h2(v.z, v.w));
}

// ---------------------------------------------------------------------------
// HMMA conv1x1, fp16 operands, fp32 accumulate (R13-verified: 256 thr,
// 8 warps, warp tile 32x64, block 128x128, K chunks of 64).
// KQ=true: stacked [2C, C] weight (kw‖qw); o0 >= CC -> Q16/qb.
// OMODE: 0 = fp16 O16 only; 1 = fp32 Out AND fp16 O16; 2 = fp32 only.
// ---------------------------------------------------------------------------
#define APITCH 72
#define BPITCH 136
#define SM_B (128 * APITCH)
#define CONV_SMEM ((128 * APITCH + 64 * BPITCH) * 2)   // 35,840 B

template<bool KQ, bool RELU, int NADD, int OMODE>
__global__ __launch_bounds__(256)
void conv_mma_kernel(const __half* __restrict__ W16,
                     const float* __restrict__ bias,
                     const float* __restrict__ bias2,
                     const __half* __restrict__ B16,
                     float* __restrict__ Out,
                     __half* __restrict__ O16,
                     __half* __restrict__ O16b,
                     const float* __restrict__ A1,
                     const float* __restrict__ A2)
{
    extern __shared__ __align__(16) __half smem[];
    __half* sA = smem;
    __half* sB = smem + SM_B;
    const uint32_t uA = smem_u32(sA);
    const uint32_t uB = smem_u32(sB);

    const int b  = blockIdx.z;
    int o0 = blockIdx.y * 128;
    const int l0 = blockIdx.x * 128;
    const size_t boff = (size_t)b * CC * LL;

    const float* biasp = bias;
    __half* O16p = O16;
    const int wrow0 = o0;
    if (KQ && o0 >= CC) {
        biasp = bias2;
        O16p = O16b;
        o0 -= CC;
    }

    const int tid  = threadIdx.x;
    const int wid  = tid >> 5;
    const int lane = tid & 31;
    const int wm   = wid & 3;
    const int wn   = wid >> 2;

    const int ar  = tid >> 4;
    const int ac4 = (tid & 15) * 4;
    const int bc  = tid >> 5;
    const int bl4 = (tid & 31) * 4;

    const int a_row = wm * 32 + (lane & 15);
    const int a_col = ((lane >> 4) & 1) * 8;
    const int b_row = (lane & 15);
    const int b_colb = wn * 64 + ((lane >> 4) & 1) * 8;

    float acc[2][8][4];
    #pragma unroll
    for (int mi = 0; mi < 2; mi++)
        #pragma unroll
        for (int ni = 0; ni < 8; ni++)
            #pragma unroll
            for (int q = 0; q < 4; q++) acc[mi][ni][q] = 0.0f;

    for (int ci = 0; ci < CC / 64; ci++) {
        const int c0 = ci * 64;
        if (ci) __syncthreads();

        #pragma unroll
        for (int p = 0; p < 8; p++) {
            const int row = ar + p * 16;
            *(uint2*)&sA[row * APITCH + ac4] =
                *(const uint2*)&W16[(size_t)(wrow0 + row) * CC + c0 + ac4];
        }
        #pragma unroll
        for (int p = 0; p < 8; p++) {
            const int row = bc + p * 8;
            *(uint2*)&sB[row * BPITCH + bl4] =
                *(const uint2*)&B16[boff + (size_t)(c0 + row) * LL + l0 + bl4];
        }
        __syncthreads();

        #pragma unroll
        for (int ks = 0; ks < 4; ks++) {
            const int kb = ks * 16;
            uint32_t af[2][4], bf[8][2];

            #pragma unroll
            for (int mi = 0; mi < 2; mi++) {
                const uint32_t off =
                    (uint32_t)((a_row + mi * 16) * APITCH + kb + a_col) * 2;
                ldsm_x4(af[mi], uA + off);
            }
            #pragma unroll
            for (int nq = 0; nq < 4; nq++) {
                const uint32_t off =
                    (uint32_t)((kb + b_row) * BPITCH + b_colb + nq * 16) * 2;
                uint32_t th[4];
                ldsm_x4_t(th, uB + off);
                bf[nq * 2 + 0][0] = th[0]; bf[nq * 2 + 0][1] = th[1];
                bf[nq * 2 + 1][0] = th[2]; bf[nq * 2 + 1][1] = th[3];
            }

            #pragma unroll
            for (int mi = 0; mi < 2; mi++)
                #pragma unroll
                for (int ni = 0; ni < 8; ni++)
                    mma_f16(acc[mi][ni], af[mi], bf[ni]);
        }
    }

    const int r = lane >> 2;
    const int g = lane & 3;

    #pragma unroll
    for (int mi = 0; mi < 2; mi++) {
        const int o1 = o0 + wm * 32 + mi * 16 + r;
        const int o2 = o1 + 8;
        const float bv1 = __ldg(&biasp[o1]);
        const float bv2 = __ldg(&biasp[o2]);
        #pragma unroll
        for (int ni = 0; ni < 8; ni++) {
            const int l = l0 + wn * 64 + ni * 8 + g * 2;
            float2 v01 = make_float2(acc[mi][ni][0] + bv1, acc[mi][ni][1] + bv1);
            float2 v23 = make_float2(acc[mi][ni][2] + bv2, acc[mi][ni][3] + bv2);
            if (RELU) {
                v01.x = fmaxf(v01.x, 0.f); v01.y = fmaxf(v01.y, 0.f);
                v23.x = fmaxf(v23.x, 0.f); v23.y = fmaxf(v23.y, 0.f);
            }
            const size_t i1 = boff + (size_t)o1 * LL + l;
            const size_t i2 = boff + (size_t)o2 * LL + l;
            if (NADD >= 1) {
                float2 a1v = *(const float2*)&A1[i1];
                float2 a2v = *(const float2*)&A1[i2];
                v01.x += a1v.x; v01.y += a1v.y;
                v23.x += a2v.x; v23.y += a2v.y;
            }
            if (NADD >= 2) {
                float2 a1v = *(const float2*)&A2[i1];
                float2 a2v = *(const float2*)&A2[i2];
                v01.x += a1v.x; v01.y += a1v.y;
                v23.x += a2v.x; v23.y += a2v.y;
            }
            if (OMODE >= 1) {
                *(float2*)&Out[i1] = v01;
                *(float2*)&Out[i2] = v23;
            }
            if (OMODE <= 1) {
                *(uint32_t*)&O16p[i1] = h2(v01.x, v01.y);
                *(uint32_t*)&O16p[i2] = h2(v23.x, v23.y);
            }
        }
    }
}

// ---------------------------------------------------------------------------
// HMMA scores -> E = exp(scores/1024) (fp16) + per-row sums Z (atomicAdd).
// (R11/R13-verified, unchanged.)
// ---------------------------------------------------------------------------
#define SPITCH 136
#define SC_Q (64 * SPITCH)
#define SCORES_SMEM (2 * 64 * SPITCH * 2)   // 34,816 B

__global__ __launch_bounds__(256)
void scores_mma_kernel(const __half* __restrict__ K16,
                       const __half* __restrict__ Q16,
                       __half* __restrict__ S,
                       float* __restrict__ Z)
{
    extern __shared__ __align__(16) __half smem[];
    __half* sK = smem;
    __half* sQ = smem + SC_Q;
    const uint32_t uK = smem_u32(sK);
    const uint32_t uQ = smem_u32(sQ);

    const int bh = blockIdx.z;
    const int b = bh >> 4, h = bh & 15;
    const int l0 = blockIdx.y * 128;
    const int m0 = blockIdx.x * 128;

    const size_t hoff = (size_t)b * CC * LL + (size_t)h * HD * LL;
    __half* Sb = S + (size_t)bh * LL * LL;
    float* Zb = Z + (size_t)bh * LL;

    const int tid  = threadIdx.x;
    const int wid  = tid >> 5;
    const int lane = tid & 31;
    const int wm   = wid & 3;
    const int wn   = wid >> 2;

    const int lr  = tid >> 5;
    const int lc4 = (tid & 31) * 4;

    #pragma unroll
    for (int p = 0; p < 8; p++) {
        const int row = lr + p * 8;
        *(uint2*)&sK[row * SPITCH + lc4] =
            *(const uint2*)&K16[hoff + (size_t)row * LL + l0 + lc4];
        *(uint2*)&sQ[row * SPITCH + lc4] =
            *(const uint2*)&Q16[hoff + (size_t)row * LL + m0 + lc4];
    }
    __syncthreads();

    const int a_krow = (lane & 7) + ((lane >> 4) & 1) * 8;
    const int a_mcol = wm * 32 + ((lane >> 3) & 1) * 8;
    const int b_krow = (lane & 15);
    const int b_mcol = wn * 64 + ((lane >> 4) & 1) * 8;

    float acc[2][8][4];
    #pragma unroll
    for (int mi = 0; mi < 2; mi++)
        #pragma unroll
        for (int ni = 0; ni < 8; ni++)
            #pragma unroll
            for (int q = 0; q < 4; q++) acc[mi][ni][q] = 0.0f;

    #pragma unroll
    for (int ks = 0; ks < 4; ks++) {
        const int kb = ks * 16;
        uint32_t af[2][4], bf[8][2];

        #pragma unroll
        for (int mi = 0; mi < 2; mi++) {
            const uint32_t off =
                (uint32_t)((kb + a_krow) * SPITCH + a_mcol + mi * 16) * 2;
            ldsm_x4_t(af[mi], uK + off);
        }
        #pragma unroll
        for (int nq = 0; nq < 4; nq++) {
            const uint32_t off =
                (uint32_t)((kb + b_krow) * SPITCH + b_mcol + nq * 16) * 2;
            uint32_t th[4];
            ldsm_x4_t(th, uQ + off);
            bf[nq * 2 + 0][0] = th[0]; bf[nq * 2 + 0][1] = th[1];
            bf[nq * 2 + 1][0] = th[2]; bf[nq * 2 + 1][1] = th[3];
        }

        #pragma unroll
        for (int mi = 0; mi < 2; mi++)
            #pragma unroll
            for (int ni = 0; ni < 8; ni++)
                mma_f16(acc[mi][ni], af[mi], bf[ni]);
    }

    const int r = lane >> 2;
    const int g = lane & 3;
    const float scale = 1.0f / 1024.0f;

    #pragma unroll
    for (int mi = 0; mi < 2; mi++) {
        const int l1 = l0 + wm * 32 + mi * 16 + r;
        const int l2 = l1 + 8;
        float rs1 = 0.0f, rs2 = 0.0f;
        #pragma unroll
        for (int ni = 0; ni < 8; ni++) {
            const int m = m0 + wn * 64 + ni * 8 + g * 2;
            const float e0 = __expf(acc[mi][ni][0] * scale);
            const float e1 = __expf(acc[mi][ni][1] * scale);
            const float e2 = __expf(acc[mi][ni][2] * scale);
            const float e3 = __expf(acc[mi][ni][3] * scale);
            *(uint32_t*)&Sb[(size_t)l1 * LL + m] = h2(e0, e1);
            *(uint32_t*)&Sb[(size_t)l2 * LL + m] = h2(e2, e3);
            rs1 += e0 + e1;
            rs2 += e2 + e3;
        }
        rs1 += __shfl_xor_sync(0xffffffffu, rs1, 1);
        rs1 += __shfl_xor_sync(0xffffffffu, rs1, 2);
        rs2 += __shfl_xor_sync(0xffffffffu, rs2, 1);
        rs2 += __shfl_xor_sync(0xffffffffu, rs2, 2);
        if (g == 0) {
            atomicAdd(&Zb[l1], rs1);
            atomicAdd(&Zb[l2], rs2);
        }
    }
}

// ---------------------------------------------------------------------------
// HMMA AV: O = (1/XS_SCALE) * XS @ E  (fp16 XS input, R13 shape) with
// REGISTER PREFETCH: chunk ci+1's global loads issue right after the
// post-STS sync and complete under chunk ci's MMA phase. smem stays
// single-buffered (no occupancy cost from smem).
// ---------------------------------------------------------------------------
#define XP 72
#define PP 136
#define AV_P (64 * XP)
#define AV_SMEM ((64 * XP + 64 * PP) * 2)   // 26,624 B

__global__ __launch_bounds__(256)
void av_mma_kernel(const __half* __restrict__ XS,
                   const __half* __restrict__ Pm,
                   __half* __restrict__ O16)
{
    extern __shared__ __align__(16) __half smem[];
    __half* sX = smem;
    __half* sP = smem + AV_P;
    const uint32_t uX = smem_u32(sX);
    const uint32_t uP = smem_u32(sP);

    const int bh = blockIdx.y;
    const int b = bh >> 4, h = bh & 15;
    const int m0 = blockIdx.x * 128;

    const size_t hoff = (size_t)b * CC * LL + (size_t)h * HD * LL;
    const __half* Ab = Pm + (size_t)bh * LL * LL;

    const int tid  = threadIdx.x;
    const int wid  = tid >> 5;
    const int lane = tid & 31;
    const int wm   = wid & 3;
    const int wn   = wid >> 2;

    const int xr  = tid >> 4;          // 0..15
    const int xc4 = (tid & 15) * 4;
    const int prr = tid >> 4;          // 0..15
    const int pc8 = (tid & 15) * 8;

    const int a_row = wm * 16 + (lane & 15);
    const int a_col = ((lane >> 4) & 1) * 8;
    const int b_krow = (lane & 15);
    const int b_mcol = wn * 64 + ((lane >> 4) & 1) * 8;

    float acc[8][4];
    #pragma unroll
    for (int ni = 0; ni < 8; ni++)
        #pragma unroll
        for (int q = 0; q < 4; q++) acc[ni][q] = 0.0f;

    const int NCH = LL / 64;   // 32

    uint2 xreg[4];
    uint4 preg[4];

    // prologue: chunk 0 into registers
    #pragma unroll
    for (int p = 0; p < 4; p++) {
        xreg[p] = *(const uint2*)&XS[hoff + (size_t)(xr + p * 16) * LL + xc4];
        preg[p] = *(const uint4*)&Ab[(size_t)(prr + p * 16) * LL + m0 + pc8];
    }

    for (int ci = 0; ci < NCH; ci++) {
        // store current chunk's registers to smem
        #pragma unroll
        for (int p = 0; p < 4; p++) {
            *(uint2*)&sX[(xr + p * 16) * XP + xc4] = xreg[p];
            *(uint4*)&sP[(prr + p * 16) * PP + pc8] = preg[p];
        }
        __syncthreads();

        // prefetch next chunk into registers (overlaps with MMA below)
        if (ci + 1 < NCH) {
            const int ln = (ci + 1) * 64;
            #pragma unroll
            for (int p = 0; p < 4; p++) {
                xreg[p] = *(const uint2*)&XS[hoff + (size_t)(xr + p * 16) * LL + ln + xc4];
                preg[p] = *(const uint4*)&Ab[(size_t)(ln + prr + p * 16) * LL + m0 + pc8];
            }
        }

        #pragma unroll
        for (int ks = 0; ks < 4; ks++) {
            const int kb = ks * 16;
            uint32_t af[4], bf[8][2];

            {
                const uint32_t off = (uint32_t)(a_row * XP + kb + a_col) * 2;
                ldsm_x4(af, uX + off);
            }
            #pragma unroll
            for (int nq = 0; nq < 4; nq++) {
                const uint32_t off =
                    (uint32_t)((kb + b_krow) * PP + b_mcol + nq * 16) * 2;
                uint32_t th[4];
                ldsm_x4_t(th, uP + off);
                bf[nq * 2 + 0][0] = th[0]; bf[nq * 2 + 0][1] = th[1];
                bf[nq * 2 + 1][0] = th[2]; bf[nq * 2 + 1][1] = th[3];
            }

            #pragma unroll
            for (int ni = 0; ni < 8; ni++)
                mma_f16(acc[ni], af, bf[ni]);
        }
        __syncthreads();
    }

    const int r = lane >> 2;
    const int g = lane & 3;
    const int c1 = wm * 16 + r;
    const int c2 = c1 + 8;
    const float inv = 1.0f / XS_SCALE;

    #pragma unroll
    for (int ni = 0; ni < 8; ni++) {
        const int m = m0 + wn * 64 + ni * 8 + g * 2;
        const size_t i1 = hoff + (size_t)c1 * LL + m;
        const size_t i2 = hoff + (size_t)c2 * LL + m;
        *(uint32_t*)&O16[i1] = h2(acc[ni][0] * inv, acc[ni][1] * inv);
        *(uint32_t*)&O16[i2] = h2(acc[ni][2] * inv, acc[ni][3] * inv);
    }
}

// ---------------------------------------------------------------------------
extern "C" void kernel_launch(void* const* d_in, const int* in_sizes, int n_in,
                              void* d_out, int out_size)
{
    const float* x   = (const float*)d_in[0];
    const float* kw  = (const float*)d_in[1];
    const float* kb  = (const float*)d_in[2];
    const float* qw  = (const float*)d_in[3];
    const float* qb  = (const float*)d_in[4];
    const float* pw  = (const float*)d_in[5];
    const float* pb  = (const float*)d_in[6];
    const float* c1w = (const float*)d_in[7];
    const float* c1b = (const float*)d_in[8];
    const float* c2w = (const float*)d_in[9];
    const float* c2b = (const float*)d_in[10];
    float* out = (float*)d_out;

    __half *gX16,*gXS16,*gK16,*gQ16,*gA16,*gY16,*gT16,*gS,*gW16;
    float *gY, *gZ;
    cudaGetSymbolAddress((void**)&gX16,  g_X16);
    cudaGetSymbolAddress((void**)&gXS16, g_XS16);
    cudaGetSymbolAddress((void**)&gK16,  g_K16);
    cudaGetSymbolAddress((void**)&gQ16,  g_Q16);
    cudaGetSymbolAddress((void**)&gA16,  g_A16);
    cudaGetSymbolAddress((void**)&gY16,  g_Y16);
    cudaGetSymbolAddress((void**)&gT16,  g_T16);
    cudaGetSymbolAddress((void**)&gS,    g_S);
    cudaGetSymbolAddress((void**)&gW16,  g_W16);
    cudaGetSymbolAddress((void**)&gY,    g_Y);
    cudaGetSymbolAddress((void**)&gZ,    g_Z);

    static bool attr_done = false;
    if (!attr_done) {
        cudaFuncSetAttribute(scores_mma_kernel,
                             cudaFuncAttributeMaxDynamicSharedMemorySize, SCORES_SMEM);
        cudaFuncSetAttribute(av_mma_kernel,
                             cudaFuncAttributeMaxDynamicSharedMemorySize, AV_SMEM);
        cudaFuncSetAttribute(conv_mma_kernel<true,  false, 0, 0>,
                             cudaFuncAttributeMaxDynamicSharedMemorySize, CONV_SMEM);
        cudaFuncSetAttribute(conv_mma_kernel<false, false, 1, 1>,
                             cudaFuncAttributeMaxDynamicSharedMemorySize, CONV_SMEM);
        cudaFuncSetAttribute(conv_mma_kernel<false, true,  0, 0>,
                             cudaFuncAttributeMaxDynamicSharedMemorySize, CONV_SMEM);
        cudaFuncSetAttribute(conv_mma_kernel<false, false, 2, 2>,
                             cudaFuncAttributeMaxDynamicSharedMemorySize, CONV_SMEM);
        attr_done = true;
    }

    // fused prep: x->fp16, 5 weights->fp16, Z=0
    prep_kernel<<<PREP_BLOCKS, 256>>>(x, kw, qw, pw, c1w, c2w, gX16, gW16, gZ);

    // K and Q projections in ONE launch over the stacked [2048,1024] weight
    conv_mma_kernel<true, false, 0, 0><<<dim3(LL / 128, 2 * CC / 128, BB), 256, CONV_SMEM>>>(
        gW16, kb, qb, gX16, nullptr, gK16, gQ16, nullptr, nullptr);

    // scores -> E + row sums Z ; fold XS_SCALE/Z into X ; AV
    scores_mma_kernel<<<dim3(LL / 128, LL / 128, NBH), 256, SCORES_SMEM>>>(
        gK16, gQ16, gS, gZ);
    scalex_kernel<<<BCL / 4 / 256, 256>>>(x, gZ, gXS16);
    av_mma_kernel<<<dim3(LL / 128, NBH), 256, AV_SMEM>>>(gXS16, gS, gA16);

    // y = pconv(AO) + x   (fp32 for residual + fp16 for c1)
    conv_mma_kernel<false, false, 1, 1><<<dim3(LL / 128, CC / 128, BB), 256, CONV_SMEM>>>(
        gW16 + 2 * WELEMS, pb, nullptr, gA16, gY, gY16, nullptr, x, nullptr);
    // t = relu(c1(y)) -> fp16
    conv_mma_kernel<false, true, 0, 0><<<dim3(LL / 128, CC / 128, BB), 256, CONV_SMEM>>>(
        gW16 + 3 * WELEMS, c1b, nullptr, gY16, nullptr, gT16, nullptr, nullptr, nullptr);
    // out = c2(t) + y + x  (fp32 only)
    conv_mma_kernel<false, false, 2, 2><<<dim3(LL / 128, CC / 128, BB), 256, CONV_SMEM>>>(
        gW16 + 4 * WELEMS, c2b, nullptr, gT16, out, nullptr, nullptr, gY, x);
}